// round 13
// baseline (speedup 1.0000x reference)
#include <cuda_runtime.h>
#include <cuda_bf16.h>

// Problem: B=16, C=64, H=128, W=128
//   masked_l1[b,c] = sum_hw |pre-gt| * mask ; nonzero[b,c] = count(mask!=0)
//   loss = sum_bc( masked_l1 / max(nonzero,1) ) / B
//
// FINAL (converged, R11 configuration — best measured across 12 rounds):
//   4096 CTAs x 512 threads (SEGS=4), 2 float4/thread/tensor, 6 LDG.128
//   front-batched, __ldcs streaming loads. Per-bc scratch atomics + ONE
//   post-stream __threadfence + global ticket; last CTA finalizes
//   in-kernel and resets all scratch (deterministic graph replays).
// Evidence of convergence: 201.3MB mandatory traffic / ~5.75 TB/s
// measured streaming ceiling = ~35.0-35.5us floor; this kernel profiles
// at 35.4us, DRAM 73.0%, all compute pipes <7%. DRAM% invariant across
// occ 46-96%, regs 27-56, MLP 2-12, SEGS 4/8/16, CTA 256/512 — the
// remaining gap to 8TB/s spec is the LTS/HBM path ceiling, not SM code.

#define BATCH   16
#define CHAN    64
#define HW      (128 * 128)            // 16384 elems per (b,c)
#define NBC     (BATCH * CHAN)         // 1024
#define SEGS    4
#define NSEG    (NBC * SEGS)           // 4096 CTAs
#define SEG_V4  (HW / 4 / SEGS)        // 1024 float4 per segment
#define THREADS 512
#define NWARP   (THREADS / 32)         // 16
#define V4_PER_THREAD (SEG_V4 / THREADS)  // 2

__device__ float    g_s[NBC];
__device__ float    g_cnt[NBC];
__device__ unsigned g_ctr;

__global__ __launch_bounds__(THREADS, 4)   // 2048 thr/SM, 32 regs/thread
void l1loss_kernel(const float4* __restrict__ pre,
                   const float4* __restrict__ gt,
                   const float4* __restrict__ mask,
                   float* __restrict__ out) {
    const int seg  = blockIdx.x;            // 0..4095
    const int bc   = seg >> 2;              // 0..1023
    const int part = seg & (SEGS - 1);      // 0..3
    const long base = (long)bc * (HW / 4) + (long)part * SEG_V4 + threadIdx.x;

    // Front-batch all 6 LDG.128.
    float4 p[V4_PER_THREAD], g[V4_PER_THREAD], m[V4_PER_THREAD];
    #pragma unroll
    for (int i = 0; i < V4_PER_THREAD; i++) p[i] = __ldcs(&pre [base + (long)i * THREADS]);
    #pragma unroll
    for (int i = 0; i < V4_PER_THREAD; i++) g[i] = __ldcs(&gt  [base + (long)i * THREADS]);
    #pragma unroll
    for (int i = 0; i < V4_PER_THREAD; i++) m[i] = __ldcs(&mask[base + (long)i * THREADS]);

    float s   = 0.0f;
    float cnt = 0.0f;
    #pragma unroll
    for (int i = 0; i < V4_PER_THREAD; i++) {
        s += fabsf(p[i].x - g[i].x) * m[i].x;
        s += fabsf(p[i].y - g[i].y) * m[i].y;
        s += fabsf(p[i].z - g[i].z) * m[i].z;
        s += fabsf(p[i].w - g[i].w) * m[i].w;
        cnt += m[i].x + m[i].y;     // mask is exactly {0,1}: sum == count
        cnt += m[i].z + m[i].w;
    }

    // Warp reduce
    #pragma unroll
    for (int off = 16; off > 0; off >>= 1) {
        s   += __shfl_down_sync(0xFFFFFFFFu, s,   off);
        cnt += __shfl_down_sync(0xFFFFFFFFu, cnt, off);
    }

    __shared__ float sh_s[NWARP];
    __shared__ float sh_c[NWARP];
    __shared__ int   sh_last;
    const int lane = threadIdx.x & 31;
    const int wid  = threadIdx.x >> 5;
    if (lane == 0) { sh_s[wid] = s; sh_c[wid] = cnt; }
    __syncthreads();

    if (threadIdx.x < 32) {
        s   = (lane < NWARP) ? sh_s[lane] : 0.0f;
        cnt = (lane < NWARP) ? sh_c[lane] : 0.0f;
        #pragma unroll
        for (int off = 8; off > 0; off >>= 1) {   // reduce 16 lanes
            s   += __shfl_down_sync(0xFFFFFFFFu, s,   off);
            cnt += __shfl_down_sync(0xFFFFFFFFu, cnt, off);
        }
        if (lane == 0) {
            atomicAdd(&g_s[bc],   s);
            atomicAdd(&g_cnt[bc], cnt);
            __threadfence();
            const unsigned old = atomicAdd(&g_ctr, 1u);
            sh_last = (old == (unsigned)(NSEG - 1)) ? 1 : 0;
        }
    }
    __syncthreads();

    // Last CTA finalizes: divide per-bc, sum, write scalar, reset scratch.
    if (sh_last) {
        float ss[NBC / THREADS], cc[NBC / THREADS];
        #pragma unroll
        for (int j = 0; j < NBC / THREADS; j++) {
            const int i = threadIdx.x + j * THREADS;
            ss[j] = __ldcg(&g_s[i]);
            cc[j] = __ldcg(&g_cnt[i]);
        }
        float q = 0.0f;
        #pragma unroll
        for (int j = 0; j < NBC / THREADS; j++) {
            const int i = threadIdx.x + j * THREADS;
            q += ss[j] / fmaxf(cc[j], 1.0f);
            g_s[i]   = 0.0f;                      // reset for next replay
            g_cnt[i] = 0.0f;
        }
        #pragma unroll
        for (int off = 16; off > 0; off >>= 1)
            q += __shfl_down_sync(0xFFFFFFFFu, q, off);

        if (lane == 0) sh_s[wid] = q;
        __syncthreads();
        if (threadIdx.x < 32) {
            q = (lane < NWARP) ? sh_s[lane] : 0.0f;
            #pragma unroll
            for (int off = 8; off > 0; off >>= 1)
                q += __shfl_down_sync(0xFFFFFFFFu, q, off);
            if (lane == 0) {
                out[0] = q * (1.0f / (float)BATCH);
                g_ctr  = 0;                       // reset ticket for next replay
            }
        }
    }
}

extern "C" void kernel_launch(void* const* d_in, const int* in_sizes, int n_in,
                              void* d_out, int out_size) {
    const float4* pre  = (const float4*)d_in[0];
    const float4* gt   = (const float4*)d_in[1];
    const float4* mask = (const float4*)d_in[2];
    float* out = (float*)d_out;

    l1loss_kernel<<<NSEG, THREADS>>>(pre, gt, mask, out);
}

// round 14
// speedup vs baseline: 1.0616x; 1.0616x over previous
#include <cuda_runtime.h>
#include <cuda_bf16.h>

// Problem: B=16, C=64, H=128, W=128
//   masked_l1[b,c] = sum_hw |pre-gt| * mask ; nonzero[b,c] = count(mask!=0)
//   loss = sum_bc( masked_l1 / max(nonzero,1) ) / B
//
// FINAL FORM (R11/R13 config + int32 addressing):
//   4096 CTAs x 512 threads (SEGS=4), 2 float4/thread/tensor, 6 LDG.128
//   front-batched, __ldcs streaming. Per-bc scratch atomics + ONE
//   post-stream __threadfence + global ticket; last CTA finalizes
//   in-kernel and resets scratch (deterministic graph replays).
//   int32 indexing (4.19M float4 < 2^31): single IMAD per address vs
//   IMAD.WIDE pairs -> shorter issue-to-first-LDG chain at CTA ramp-in.
// Converged: 201.3MB mandatory / ~5.8 TB/s measured ceiling = ~34.7us
// floor; kernel profiles 35.3us, DRAM 73.3%, all compute pipes <7%.
// DRAM% invariant across occ 46-96%, regs 27-56, MLP 2-12, SEGS 4/8/16,
// CTA 256/512 — remaining gap to 8TB/s spec is the LTS/HBM path ceiling.

#define BATCH   16
#define CHAN    64
#define HW      (128 * 128)            // 16384 elems per (b,c)
#define NBC     (BATCH * CHAN)         // 1024
#define SEGS    4
#define NSEG    (NBC * SEGS)           // 4096 CTAs
#define SEG_V4  (HW / 4 / SEGS)        // 1024 float4 per segment
#define THREADS 512
#define NWARP   (THREADS / 32)         // 16
#define V4_PER_THREAD (SEG_V4 / THREADS)  // 2

__device__ float    g_s[NBC];
__device__ float    g_cnt[NBC];
__device__ unsigned g_ctr;

__global__ __launch_bounds__(THREADS, 4)   // 2048 thr/SM, 32 regs/thread
void l1loss_kernel(const float4* __restrict__ pre,
                   const float4* __restrict__ gt,
                   const float4* __restrict__ mask,
                   float* __restrict__ out) {
    const int seg  = blockIdx.x;            // 0..4095
    const int bc   = seg >> 2;              // 0..1023
    const int part = seg & (SEGS - 1);      // 0..3
    // Max index = 4096*4096 float4 = 2^24 -> int32 safe (LEA-friendly).
    const int base = bc * (HW / 4) + part * SEG_V4 + (int)threadIdx.x;

    // Front-batch all 6 LDG.128.
    float4 p[V4_PER_THREAD], g[V4_PER_THREAD], m[V4_PER_THREAD];
    #pragma unroll
    for (int i = 0; i < V4_PER_THREAD; i++) p[i] = __ldcs(&pre [base + i * THREADS]);
    #pragma unroll
    for (int i = 0; i < V4_PER_THREAD; i++) g[i] = __ldcs(&gt  [base + i * THREADS]);
    #pragma unroll
    for (int i = 0; i < V4_PER_THREAD; i++) m[i] = __ldcs(&mask[base + i * THREADS]);

    float s   = 0.0f;
    float cnt = 0.0f;
    #pragma unroll
    for (int i = 0; i < V4_PER_THREAD; i++) {
        s += fabsf(p[i].x - g[i].x) * m[i].x;
        s += fabsf(p[i].y - g[i].y) * m[i].y;
        s += fabsf(p[i].z - g[i].z) * m[i].z;
        s += fabsf(p[i].w - g[i].w) * m[i].w;
        cnt += m[i].x + m[i].y;     // mask is exactly {0,1}: sum == count
        cnt += m[i].z + m[i].w;
    }

    // Warp reduce
    #pragma unroll
    for (int off = 16; off > 0; off >>= 1) {
        s   += __shfl_down_sync(0xFFFFFFFFu, s,   off);
        cnt += __shfl_down_sync(0xFFFFFFFFu, cnt, off);
    }

    __shared__ float sh_s[NWARP];
    __shared__ float sh_c[NWARP];
    __shared__ int   sh_last;
    const int lane = threadIdx.x & 31;
    const int wid  = threadIdx.x >> 5;
    if (lane == 0) { sh_s[wid] = s; sh_c[wid] = cnt; }
    __syncthreads();

    if (threadIdx.x < 32) {
        s   = (lane < NWARP) ? sh_s[lane] : 0.0f;
        cnt = (lane < NWARP) ? sh_c[lane] : 0.0f;
        #pragma unroll
        for (int off = 8; off > 0; off >>= 1) {   // reduce 16 lanes
            s   += __shfl_down_sync(0xFFFFFFFFu, s,   off);
            cnt += __shfl_down_sync(0xFFFFFFFFu, cnt, off);
        }
        if (lane == 0) {
            atomicAdd(&g_s[bc],   s);
            atomicAdd(&g_cnt[bc], cnt);
            __threadfence();
            const unsigned old = atomicAdd(&g_ctr, 1u);
            sh_last = (old == (unsigned)(NSEG - 1)) ? 1 : 0;
        }
    }
    __syncthreads();

    // Last CTA finalizes: divide per-bc, sum, write scalar, reset scratch.
    if (sh_last) {
        float ss[NBC / THREADS], cc[NBC / THREADS];
        #pragma unroll
        for (int j = 0; j < NBC / THREADS; j++) {
            const int i = threadIdx.x + j * THREADS;
            ss[j] = __ldcg(&g_s[i]);
            cc[j] = __ldcg(&g_cnt[i]);
        }
        float q = 0.0f;
        #pragma unroll
        for (int j = 0; j < NBC / THREADS; j++) {
            const int i = threadIdx.x + j * THREADS;
            q += ss[j] / fmaxf(cc[j], 1.0f);
            g_s[i]   = 0.0f;                      // reset for next replay
            g_cnt[i] = 0.0f;
        }
        #pragma unroll
        for (int off = 16; off > 0; off >>= 1)
            q += __shfl_down_sync(0xFFFFFFFFu, q, off);

        if (lane == 0) sh_s[wid] = q;
        __syncthreads();
        if (threadIdx.x < 32) {
            q = (lane < NWARP) ? sh_s[lane] : 0.0f;
            #pragma unroll
            for (int off = 8; off > 0; off >>= 1)
                q += __shfl_down_sync(0xFFFFFFFFu, q, off);
            if (lane == 0) {
                out[0] = q * (1.0f / (float)BATCH);
                g_ctr  = 0;                       // reset ticket for next replay
            }
        }
    }
}

extern "C" void kernel_launch(void* const* d_in, const int* in_sizes, int n_in,
                              void* d_out, int out_size) {
    const float4* pre  = (const float4*)d_in[0];
    const float4* gt   = (const float4*)d_in[1];
    const float4* mask = (const float4*)d_in[2];
    float* out = (float*)d_out;

    l1loss_kernel<<<NSEG, THREADS>>>(pre, gt, mask, out);
}